// round 8
// baseline (speedup 1.0000x reference)
#include <cuda_runtime.h>
#include <stdint.h>
#include <math.h>

#define BATCH 16
#define CH    256
#define NSP   1024      // H*W
#define NH    2
#define HD    128
#define NG    4
#define CPG   64        // channels per group

// ---------------- packed f32x2 helpers (sm_103a FFMA2 path) ------------------
__device__ __forceinline__ uint64_t dup2(float v) {
    uint64_t r; asm("mov.b64 %0, {%1,%1};" : "=l"(r) : "f"(v)); return r;
}
__device__ __forceinline__ uint64_t pk2(float lo, float hi) {
    uint64_t r; asm("mov.b64 %0, {%1,%2};" : "=l"(r) : "f"(lo), "f"(hi)); return r;
}
__device__ __forceinline__ float2 up2(uint64_t v) {
    float2 f; asm("mov.b64 {%0,%1}, %2;" : "=f"(f.x), "=f"(f.y) : "l"(v)); return f;
}
__device__ __forceinline__ void fma2(uint64_t &d, uint64_t a, uint64_t b) {
    asm("fma.rn.f32x2 %0, %1, %2, %0;" : "+l"(d) : "l"(a), "l"(b));
}
__device__ __forceinline__ void mul2(uint64_t &d, uint64_t a) {
    asm("mul.rn.f32x2 %0, %0, %1;" : "+l"(d) : "l"(a));
}
__device__ __forceinline__ void add2(uint64_t &d, uint64_t a) {
    asm("add.rn.f32x2 %0, %0, %1;" : "+l"(d) : "l"(a));
}

// ---------------- scratch (static device globals; no allocation) -------------
__device__ float g_scale[BATCH*CH];        // per (b,c) affine scale after GN
__device__ float g_bias [BATCH*CH];        // per (b,c) affine bias  after GN
__device__ float g_q[BATCH*CH*NSP];
__device__ float g_k[BATCH*CH*NSP];
__device__ float g_v[BATCH*CH*NSP];
__device__ float g_o[BATCH*CH*NSP];

// ---------------- 1) GroupNorm stats -> per-channel scale/bias ---------------
__global__ void gn_stats_kernel(const float* __restrict__ x,
                                const float* __restrict__ gn_w,
                                const float* __restrict__ gn_b) {
    int bg = blockIdx.x;               // 0..63
    int b = bg / NG, g = bg % NG;
    const float* xp = x + ((size_t)b*CH + (size_t)g*CPG)*NSP;
    int tid = threadIdx.x;

    float s = 0.f, s2 = 0.f;
    for (int i = tid; i < CPG*NSP/4; i += 256) {
        float4 v = ((const float4*)xp)[i];
        s  += (v.x + v.y) + (v.z + v.w);
        s2 += (v.x*v.x + v.y*v.y) + (v.z*v.z + v.w*v.w);
    }
    __shared__ float ss[256], ss2[256];
    ss[tid] = s; ss2[tid] = s2;
    __syncthreads();
    for (int o = 128; o > 0; o >>= 1) {
        if (tid < o) { ss[tid] += ss[tid+o]; ss2[tid] += ss2[tid+o]; }
        __syncthreads();
    }
    __shared__ float sh_mean, sh_rstd;
    if (tid == 0) {
        const float inv = 1.0f / (float)(CPG*NSP);
        float mean = ss[0] * inv;
        float var  = ss2[0] * inv - mean*mean;
        sh_mean = mean;
        sh_rstd = rsqrtf(var + 1e-5f);
    }
    __syncthreads();
    if (tid < CPG) {
        int c = g*CPG + tid;
        float sc = sh_rstd * gn_w[c];
        g_scale[b*CH + c] = sc;
        g_bias [b*CH + c] = gn_b[c] - sh_mean * sc;
    }
}

// ---------------- 2) fused GN-apply + QKV GEMM (FFMA2) -----------------------
// q/k/v[b,o,n] = sum_c W[o,c] * (scale[b,c]*x[b,c,n] + bias[b,c])
__global__ void qkv_gemm_kernel(const float* __restrict__ x,
                                const float* __restrict__ wq,
                                const float* __restrict__ wk,
                                const float* __restrict__ wv) {
    int b  = blockIdx.z;
    int m0 = blockIdx.y * 64;
    int n0 = blockIdx.x * 64;
    int tid = threadIdx.x;

    __shared__ float As[3][16][64];   // [w][k][m]
    __shared__ float Bs[16][64];      // [k][n]

    const float* W0 = wq; const float* W1 = wk; const float* W2 = wv;

    // acc2[w][i][p]: i = m sub-row 0..3, p = packed n pair 0..1 (covers 4 n)
    uint64_t acc2[3][4][2];
    #pragma unroll
    for (int w = 0; w < 3; w++)
        #pragma unroll
        for (int i = 0; i < 4; i++) { acc2[w][i][0] = 0ull; acc2[w][i][1] = 0ull; }

    int arow = tid >> 2;          // m within tile (0..63)
    int acol = (tid & 3) * 4;     // k (0..15)
    int brow = tid >> 4;          // k (0..15)
    int bcol = (tid & 15) * 4;    // n (0..63)
    int ty = tid >> 4, tx = tid & 15;

    const float* xb  = x + (size_t)b*CH*NSP;
    const float* scp = g_scale + b*CH;
    const float* bip = g_bias  + b*CH;

    for (int k0 = 0; k0 < CH; k0 += 16) {
        {
            float4 a0 = *(const float4*)&W0[(size_t)(m0+arow)*CH + k0 + acol];
            float4 a1 = *(const float4*)&W1[(size_t)(m0+arow)*CH + k0 + acol];
            float4 a2 = *(const float4*)&W2[(size_t)(m0+arow)*CH + k0 + acol];
            As[0][acol+0][arow]=a0.x; As[0][acol+1][arow]=a0.y; As[0][acol+2][arow]=a0.z; As[0][acol+3][arow]=a0.w;
            As[1][acol+0][arow]=a1.x; As[1][acol+1][arow]=a1.y; As[1][acol+2][arow]=a1.z; As[1][acol+3][arow]=a1.w;
            As[2][acol+0][arow]=a2.x; As[2][acol+1][arow]=a2.y; As[2][acol+2][arow]=a2.z; As[2][acol+3][arow]=a2.w;
        }
        {
            int k = k0 + brow;
            float4 bv = *(const float4*)&xb[(size_t)k*NSP + n0 + bcol];
            float s = scp[k], bi = bip[k];
            bv.x = fmaf(bv.x, s, bi);
            bv.y = fmaf(bv.y, s, bi);
            bv.z = fmaf(bv.z, s, bi);
            bv.w = fmaf(bv.w, s, bi);
            *(float4*)&Bs[brow][bcol] = bv;
        }
        __syncthreads();
        #pragma unroll
        for (int kk = 0; kk < 16; kk++) {
            const uint64_t* bp = (const uint64_t*)&Bs[kk][tx*4];
            uint64_t b0 = bp[0], b1 = bp[1];
            #pragma unroll
            for (int w = 0; w < 3; w++) {
                float4 av = *(const float4*)&As[w][kk][ty*4];
                uint64_t a;
                a = dup2(av.x); fma2(acc2[w][0][0], a, b0); fma2(acc2[w][0][1], a, b1);
                a = dup2(av.y); fma2(acc2[w][1][0], a, b0); fma2(acc2[w][1][1], a, b1);
                a = dup2(av.z); fma2(acc2[w][2][0], a, b0); fma2(acc2[w][2][1], a, b1);
                a = dup2(av.w); fma2(acc2[w][3][0], a, b0); fma2(acc2[w][3][1], a, b1);
            }
        }
        __syncthreads();
    }

    #pragma unroll
    for (int i = 0; i < 4; i++) {
        size_t base = ((size_t)b*CH + m0 + ty*4 + i)*NSP + n0 + tx*4;
        ((uint64_t*)&g_q[base])[0] = acc2[0][i][0]; ((uint64_t*)&g_q[base])[1] = acc2[0][i][1];
        ((uint64_t*)&g_k[base])[0] = acc2[1][i][0]; ((uint64_t*)&g_k[base])[1] = acc2[1][i][1];
        ((uint64_t*)&g_v[base])[0] = acc2[2][i][0]; ((uint64_t*)&g_v[base])[1] = acc2[2][i][1];
    }
}

// ---------------- 3) fused flash attention (FFMA2 core) ----------------------
#define SQS 68
#define FL_SMEM_FLOATS (128*SQS + 128*SQS + 64*SQS + 64*SQS + 192)
#define FL_SMEM_BYTES  (FL_SMEM_FLOATS*4)

__global__ void __launch_bounds__(256, 2) flash_kernel() {
    extern __shared__ float sm[];
    float* Qs   = sm;                      // [128][SQS]
    float* KV   = Qs + 128*SQS;            // [128][SQS]
    float* Ss   = KV + 128*SQS;            // [64][SQS]
    float* Ps   = Ss + 64*SQS;             // [64][SQS]  (P transposed: [j][i])
    float* mrow = Ps + 64*SQS;             // [64]
    float* lrow = mrow + 64;               // [64]
    float* arow = lrow + 64;               // [64]

    const int bh = blockIdx.y;             // 0..31
    const int b  = bh >> 1, h = bh & 1;
    const int i0 = blockIdx.x * 64;
    const int tid = threadIdx.x;
    const int ty = tid >> 4, tx = tid & 15;

    const size_t hdbase = ((size_t)b*CH + (size_t)h*HD)*NSP;
    const float* qp = g_q + hdbase;
    const float* kp = g_k + hdbase;
    const float* vp = g_v + hdbase;

    const float scale = 0.044194173824159216f;   // (256*2)^-0.5

    // load Q tile: Qs[c][i]
    {
        int c = ty, col4 = tx * 4;
        #pragma unroll
        for (int r = 0; r < 8; r++, c += 16)
            *(float4*)&Qs[c*SQS + col4] = *(const float4*)&qp[(size_t)c*NSP + i0 + col4];
    }
    if (tid < 64) { mrow[tid] = -1e30f; lrow[tid] = 0.f; }

    // O accumulators: c = ty*8+cc, i pairs: [cc][p], p=0 -> (i0,i1), p=1 -> (i2,i3)
    uint64_t O2[8][2];
    #pragma unroll
    for (int cc = 0; cc < 8; cc++) { O2[cc][0] = 0ull; O2[cc][1] = 0ull; }

    __syncthreads();

    const int srow = tid >> 2;             // softmax row (0..63)
    const int sq   = tid & 3;              // quarter of the row

    for (int j0 = 0; j0 < NSP; j0 += 64) {
        // ---- load K tile into KV ----
        {
            int c = ty, col4 = tx * 4;
            #pragma unroll
            for (int r = 0; r < 8; r++, c += 16)
                *(float4*)&KV[c*SQS + col4] = *(const float4*)&kp[(size_t)c*NSP + j0 + col4];
        }
        __syncthreads();

        // ---- S = scale * Q^T K  (FFMA2: pairs along j) ----
        uint64_t s2[4][2];
        #pragma unroll
        for (int i = 0; i < 4; i++) { s2[i][0] = 0ull; s2[i][1] = 0ull; }

        #pragma unroll 8
        for (int c = 0; c < HD; c++) {
            float4 q4 = *(const float4*)&Qs[c*SQS + ty*4];
            const uint64_t* kp2 = (const uint64_t*)&KV[c*SQS + tx*4];
            uint64_t k0p = kp2[0], k1p = kp2[1];
            uint64_t a;
            a = dup2(q4.x); fma2(s2[0][0], a, k0p); fma2(s2[0][1], a, k1p);
            a = dup2(q4.y); fma2(s2[1][0], a, k0p); fma2(s2[1][1], a, k1p);
            a = dup2(q4.z); fma2(s2[2][0], a, k0p); fma2(s2[2][1], a, k1p);
            a = dup2(q4.w); fma2(s2[3][0], a, k0p); fma2(s2[3][1], a, k1p);
        }
        {
            uint64_t sc2 = dup2(scale);
            #pragma unroll
            for (int i = 0; i < 4; i++) {
                mul2(s2[i][0], sc2); mul2(s2[i][1], sc2);
                uint64_t* sp = (uint64_t*)&Ss[(ty*4+i)*SQS + tx*4];
                sp[0] = s2[i][0]; sp[1] = s2[i][1];
            }
        }
        __syncthreads();   // Ss ready; everyone done reading K tile

        // ---- load V tile into KV (overwrites K) ----
        {
            int c = ty, col4 = tx * 4;
            #pragma unroll
            for (int r = 0; r < 8; r++, c += 16)
                *(float4*)&KV[c*SQS + col4] = *(const float4*)&vp[(size_t)c*NSP + j0 + col4];
        }

        // ---- online softmax for 16 entries of one row ----
        {
            float4 v0 = *(const float4*)&Ss[srow*SQS + sq*16 + 0];
            float4 v1 = *(const float4*)&Ss[srow*SQS + sq*16 + 4];
            float4 v2 = *(const float4*)&Ss[srow*SQS + sq*16 + 8];
            float4 v3 = *(const float4*)&Ss[srow*SQS + sq*16 + 12];
            float mloc = fmaxf(fmaxf(fmaxf(v0.x,v0.y),fmaxf(v0.z,v0.w)),
                               fmaxf(fmaxf(v1.x,v1.y),fmaxf(v1.z,v1.w)));
            mloc = fmaxf(mloc, fmaxf(fmaxf(fmaxf(v2.x,v2.y),fmaxf(v2.z,v2.w)),
                                     fmaxf(fmaxf(v3.x,v3.y),fmaxf(v3.z,v3.w))));
            mloc = fmaxf(mloc, __shfl_xor_sync(0xffffffffu, mloc, 1));
            mloc = fmaxf(mloc, __shfl_xor_sync(0xffffffffu, mloc, 2));
            float mold = mrow[srow];
            float mnew = fmaxf(mold, mloc);

            float p[16];
            p[0]=__expf(v0.x-mnew); p[1]=__expf(v0.y-mnew); p[2]=__expf(v0.z-mnew); p[3]=__expf(v0.w-mnew);
            p[4]=__expf(v1.x-mnew); p[5]=__expf(v1.y-mnew); p[6]=__expf(v1.z-mnew); p[7]=__expf(v1.w-mnew);
            p[8]=__expf(v2.x-mnew); p[9]=__expf(v2.y-mnew); p[10]=__expf(v2.z-mnew); p[11]=__expf(v2.w-mnew);
            p[12]=__expf(v3.x-mnew); p[13]=__expf(v3.y-mnew); p[14]=__expf(v3.z-mnew); p[15]=__expf(v3.w-mnew);
            float sum = 0.f;
            #pragma unroll
            for (int k = 0; k < 16; k++) {
                Ps[(sq*16 + k)*SQS + srow] = p[k];    // transpose: Ps[j][i]
                sum += p[k];
            }
            sum += __shfl_xor_sync(0xffffffffu, sum, 1);
            sum += __shfl_xor_sync(0xffffffffu, sum, 2);
            if (sq == 0) {
                float al = __expf(mold - mnew);
                arow[srow] = al;
                mrow[srow] = mnew;
                lrow[srow] = lrow[srow]*al + sum;
            }
        }
        __syncthreads();   // Ps, alpha, V all ready

        // ---- rescale O, accumulate O += V * P^T (FFMA2) ----
        {
            uint64_t a01 = pk2(arow[tx*4+0], arow[tx*4+1]);
            uint64_t a23 = pk2(arow[tx*4+2], arow[tx*4+3]);
            #pragma unroll
            for (int cc = 0; cc < 8; cc++) { mul2(O2[cc][0], a01); mul2(O2[cc][1], a23); }
        }
        #pragma unroll 4
        for (int j4 = 0; j4 < 64; j4 += 4) {
            const uint64_t* q0 = (const uint64_t*)&Ps[(j4+0)*SQS + tx*4];
            const uint64_t* q1 = (const uint64_t*)&Ps[(j4+1)*SQS + tx*4];
            const uint64_t* q2 = (const uint64_t*)&Ps[(j4+2)*SQS + tx*4];
            const uint64_t* q3 = (const uint64_t*)&Ps[(j4+3)*SQS + tx*4];
            uint64_t p0a=q0[0], p0b=q0[1], p1a=q1[0], p1b=q1[1];
            uint64_t p2a=q2[0], p2b=q2[1], p3a=q3[0], p3b=q3[1];
            #pragma unroll
            for (int cc = 0; cc < 8; cc++) {
                float4 v4 = *(const float4*)&KV[(ty*8+cc)*SQS + j4];
                uint64_t d;
                d = dup2(v4.x); fma2(O2[cc][0], d, p0a); fma2(O2[cc][1], d, p0b);
                d = dup2(v4.y); fma2(O2[cc][0], d, p1a); fma2(O2[cc][1], d, p1b);
                d = dup2(v4.z); fma2(O2[cc][0], d, p2a); fma2(O2[cc][1], d, p2b);
                d = dup2(v4.w); fma2(O2[cc][0], d, p3a); fma2(O2[cc][1], d, p3b);
            }
        }
        __syncthreads();   // done with Ps / V before next tile overwrites
    }

    // ---- epilogue: divide by l and store ----
    {
        uint64_t inv01 = pk2(1.0f/lrow[tx*4+0], 1.0f/lrow[tx*4+1]);
        uint64_t inv23 = pk2(1.0f/lrow[tx*4+2], 1.0f/lrow[tx*4+3]);
        #pragma unroll
        for (int cc = 0; cc < 8; cc++) {
            mul2(O2[cc][0], inv01);
            mul2(O2[cc][1], inv23);
            size_t base = hdbase + (size_t)(ty*8+cc)*NSP + i0 + tx*4;
            ((uint64_t*)&g_o[base])[0] = O2[cc][0];
            ((uint64_t*)&g_o[base])[1] = O2[cc][1];
        }
    }
}

// ---------------- 4) proj GEMM + residual (FFMA2) ----------------------------
// out[b,o,n] = sum_c wp[o,c] * g_o[b,c,n] + x[b,o,n]
__global__ void proj_kernel(const float* __restrict__ x,
                            const float* __restrict__ wp,
                            float* __restrict__ out) {
    int b  = blockIdx.z;
    int m0 = blockIdx.y * 64;
    int n0 = blockIdx.x * 64;
    int tid = threadIdx.x;

    __shared__ float As[16][64];    // [k][m]
    __shared__ float Bs[16][64];    // [k][n]

    uint64_t acc2[4][2];
    #pragma unroll
    for (int i = 0; i < 4; i++) { acc2[i][0] = 0ull; acc2[i][1] = 0ull; }

    int arow = tid >> 2;
    int acol = (tid & 3) * 4;
    int brow = tid >> 4;
    int bcol = (tid & 15) * 4;
    int ty = tid >> 4, tx = tid & 15;

    const float* ob = g_o + (size_t)b*CH*NSP;

    for (int k0 = 0; k0 < CH; k0 += 16) {
        {
            float4 av = *(const float4*)&wp[(size_t)(m0+arow)*CH + k0 + acol];
            As[acol+0][arow]=av.x; As[acol+1][arow]=av.y; As[acol+2][arow]=av.z; As[acol+3][arow]=av.w;
        }
        *(float4*)&Bs[brow][bcol] = *(const float4*)&ob[(size_t)(k0+brow)*NSP + n0 + bcol];
        __syncthreads();
        #pragma unroll
        for (int kk = 0; kk < 16; kk++) {
            const uint64_t* bp = (const uint64_t*)&Bs[kk][tx*4];
            uint64_t b0 = bp[0], b1 = bp[1];
            float4 av = *(const float4*)&As[kk][ty*4];
            uint64_t a;
            a = dup2(av.x); fma2(acc2[0][0], a, b0); fma2(acc2[0][1], a, b1);
            a = dup2(av.y); fma2(acc2[1][0], a, b0); fma2(acc2[1][1], a, b1);
            a = dup2(av.z); fma2(acc2[2][0], a, b0); fma2(acc2[2][1], a, b1);
            a = dup2(av.w); fma2(acc2[3][0], a, b0); fma2(acc2[3][1], a, b1);
        }
        __syncthreads();
    }

    #pragma unroll
    for (int i = 0; i < 4; i++) {
        size_t base = ((size_t)b*CH + m0 + ty*4 + i)*NSP + n0 + tx*4;
        const uint64_t* rp = (const uint64_t*)&x[base];
        add2(acc2[i][0], rp[0]);
        add2(acc2[i][1], rp[1]);
        ((uint64_t*)&out[base])[0] = acc2[i][0];
        ((uint64_t*)&out[base])[1] = acc2[i][1];
    }
}

// -----------------------------------------------------------------------------
extern "C" void kernel_launch(void* const* d_in, const int* in_sizes, int n_in,
                              void* d_out, int out_size) {
    const float* x    = (const float*)d_in[0];
    const float* gn_w = (const float*)d_in[1];
    const float* gn_b = (const float*)d_in[2];
    const float* wq   = (const float*)d_in[3];
    const float* wk   = (const float*)d_in[4];
    const float* wv   = (const float*)d_in[5];
    const float* wp   = (const float*)d_in[6];
    float* out        = (float*)d_out;

    cudaFuncSetAttribute(flash_kernel,
                         cudaFuncAttributeMaxDynamicSharedMemorySize,
                         FL_SMEM_BYTES);

    gn_stats_kernel<<<BATCH*NG, 256>>>(x, gn_w, gn_b);
    qkv_gemm_kernel<<<dim3(NSP/64, CH/64, BATCH), 256>>>(x, wq, wk, wv);
    flash_kernel<<<dim3(NSP/64, BATCH*NH), 256, FL_SMEM_BYTES>>>();
    proj_kernel<<<dim3(NSP/64, CH/64, BATCH), 256>>>(x, wp, out);
}

// round 11
// speedup vs baseline: 1.8030x; 1.8030x over previous
#include <cuda_runtime.h>
#include <stdint.h>
#include <math.h>

#define BATCH 16
#define CH    256
#define NSP   1024
#define NH    2
#define HD    128
#define NG    4
#define CPG   64

// ---------------- scratch (static device globals; no allocation) -------------
__device__ float g_scale[BATCH*CH];
__device__ float g_bias [BATCH*CH];
__device__ float g_xt[(size_t)BATCH*NSP*CH];        // normalized x, [b][n][c]
__device__ float g_q [(size_t)BATCH*NH*NSP*HD];     // [bh][i][c]
__device__ float g_k [(size_t)BATCH*NH*NSP*HD];     // [bh][j][c]
__device__ float g_v [(size_t)BATCH*NH*HD*NSP];     // [bh][c][j]
__device__ float g_p [(size_t)BATCH*NH*NSP*NSP];    // [bh][i][j]
__device__ float g_oat[(size_t)BATCH*NSP*CH];       // [b][n][c]

// ---------------- helpers ----------------------------------------------------
__device__ __forceinline__ uint32_t f2tf32(float f) {
    uint32_t r; asm("cvt.rna.tf32.f32 %0, %1;" : "=r"(r) : "f"(f)); return r;
}
__device__ __forceinline__ void mma8(float d[4], const uint32_t a[4], const uint32_t b[2]) {
    asm volatile("mma.sync.aligned.m16n8k8.row.col.f32.tf32.tf32.f32 "
        "{%0,%1,%2,%3}, {%4,%5,%6,%7}, {%8,%9}, {%0,%1,%2,%3};"
        : "+f"(d[0]), "+f"(d[1]), "+f"(d[2]), "+f"(d[3])
        : "r"(a[0]), "r"(a[1]), "r"(a[2]), "r"(a[3]), "r"(b[0]), "r"(b[1]));
}

// SMEM tile stride in floats: 32 K-chunk + 4 pad (keeps float4 align, no conflicts)
#define TS 36

// ---------------- shared 128x128 GEMM core -----------------------------------
// C[128][128] (block tile) = A[128][K] * B[128][K]^T, tf32 inputs, fp32 accum.
// 256 threads; warp w: wm=w&3 (m), wn=w>>2 (n); warp tile 32(m) x 64(n).
// Accums d[ms][ns][4]: ms=0..1 (16-row subtiles), ns=0..7 (8-col subtiles).
__device__ __forceinline__ void gemm128_core(
    const float* __restrict__ A, int ldA,
    const float* __restrict__ B, int ldB,
    int K, uint32_t* As, uint32_t* Bs,
    float d[2][8][4])
{
    const int tid  = threadIdx.x;
    const int lane = tid & 31;
    const int w    = tid >> 5;
    const int wm   = w & 3, wn = w >> 2;
    const int g    = lane >> 2, tig = lane & 3;

    const int srow  = tid >> 1;          // staging row (0..127)
    const int shalf = (tid & 1) * 16;    // staging k-offset

    const float* Ar = A + (size_t)srow*ldA + shalf;
    const float* Br = B + (size_t)srow*ldB + shalf;
    uint32_t* AsW = As + srow*TS + shalf;
    uint32_t* BsW = Bs + srow*TS + shalf;

    for (int k0 = 0; k0 < K; k0 += 32) {
        // ---- stage 32-wide K chunk, converting fp32 -> tf32 bits ----
        #pragma unroll
        for (int f = 0; f < 4; f++) {
            float4 va = *(const float4*)(Ar + k0 + f*4);
            float4 vb = *(const float4*)(Br + k0 + f*4);
            uint4 ua = make_uint4(f2tf32(va.x), f2tf32(va.y), f2tf32(va.z), f2tf32(va.w));
            uint4 ub = make_uint4(f2tf32(vb.x), f2tf32(vb.y), f2tf32(vb.z), f2tf32(vb.w));
            *(uint4*)(AsW + f*4) = ua;
            *(uint4*)(BsW + f*4) = ub;
        }
        __syncthreads();

        // ---- 4 k-steps of 8 ----
        #pragma unroll
        for (int ks = 0; ks < 4; ks++) {
            uint32_t a[2][4], b[8][2];
            #pragma unroll
            for (int ms = 0; ms < 2; ms++) {
                const uint32_t* ap = As + (wm*32 + ms*16 + g)*TS + ks*8 + tig;
                a[ms][0] = ap[0];
                a[ms][1] = ap[8*TS];
                a[ms][2] = ap[4];
                a[ms][3] = ap[8*TS + 4];
            }
            #pragma unroll
            for (int ns = 0; ns < 8; ns++) {
                const uint32_t* bp = Bs + (wn*64 + ns*8 + g)*TS + ks*8 + tig;
                b[ns][0] = bp[0];
                b[ns][1] = bp[4];
            }
            #pragma unroll
            for (int ms = 0; ms < 2; ms++)
                #pragma unroll
                for (int ns = 0; ns < 8; ns++)
                    mma8(d[ms][ns], a[ms], b[ns]);
        }
        __syncthreads();
    }
}

// Epilogue coordinates for this thread: rows (tile_m + wm*32 + ms*16 + g [+8]),
// cols (tile_n + wn*64 + ns*8 + 2*tig [+1]).
#define EPI_SETUP() \
    const int lane = threadIdx.x & 31; const int w = threadIdx.x >> 5;          \
    const int wm = w & 3, wn = w >> 2; const int g = lane >> 2, tig = lane & 3;

// ---------------- 1) GroupNorm stats -----------------------------------------
__global__ void gn_stats_kernel(const float* __restrict__ x,
                                const float* __restrict__ gn_w,
                                const float* __restrict__ gn_b) {
    int bg = blockIdx.x;
    int b = bg / NG, gq = bg % NG;
    const float* xp = x + ((size_t)b*CH + (size_t)gq*CPG)*NSP;
    int tid = threadIdx.x;
    float s = 0.f, s2 = 0.f;
    for (int i = tid; i < CPG*NSP/4; i += 256) {
        float4 v = ((const float4*)xp)[i];
        s  += (v.x + v.y) + (v.z + v.w);
        s2 += (v.x*v.x + v.y*v.y) + (v.z*v.z + v.w*v.w);
    }
    __shared__ float ss[256], ss2[256];
    ss[tid] = s; ss2[tid] = s2;
    __syncthreads();
    for (int o = 128; o > 0; o >>= 1) {
        if (tid < o) { ss[tid] += ss[tid+o]; ss2[tid] += ss2[tid+o]; }
        __syncthreads();
    }
    __shared__ float sh_mean, sh_rstd;
    if (tid == 0) {
        const float inv = 1.0f / (float)(CPG*NSP);
        float mean = ss[0] * inv;
        float var  = ss2[0] * inv - mean*mean;
        sh_mean = mean; sh_rstd = rsqrtf(var + 1e-5f);
    }
    __syncthreads();
    if (tid < CPG) {
        int c = gq*CPG + tid;
        float sc = sh_rstd * gn_w[c];
        g_scale[b*CH + c] = sc;
        g_bias [b*CH + c] = gn_b[c] - sh_mean * sc;
    }
}

// ---------------- 2) normalize + transpose: xt[b][n][c] ----------------------
__global__ void transpose_kernel(const float* __restrict__ x) {
    __shared__ float t[32][33];
    int b = blockIdx.z, c0 = blockIdx.y*32, n0 = blockIdx.x*32;
    int tx = threadIdx.x, ty = threadIdx.y;
    #pragma unroll
    for (int i = 0; i < 4; i++) {
        int c = c0 + ty + i*8;
        float sc = g_scale[b*CH + c], bi = g_bias[b*CH + c];
        t[ty+i*8][tx] = fmaf(x[((size_t)b*CH + c)*NSP + n0 + tx], sc, bi);
    }
    __syncthreads();
    #pragma unroll
    for (int i = 0; i < 4; i++) {
        int n = n0 + ty + i*8;
        g_xt[((size_t)b*NSP + n)*CH + c0 + tx] = t[tx][ty+i*8];
    }
}

// ---------------- 3) Q / K GEMM: D[i][c'] = xt * W^T -------------------------
__global__ void __launch_bounds__(256, 2) qk_kernel(const float* __restrict__ wq,
                                                    const float* __restrict__ wk) {
    __shared__ uint32_t As[128*TS], Bs[128*TS];
    int it = blockIdx.x, yz = blockIdx.y, b = blockIdx.z;
    int h = yz >> 1, isk = yz & 1;

    const float* A = g_xt + ((size_t)b*NSP + it*128)*CH;
    const float* B = (isk ? wk : wq) + (size_t)h*HD*CH;
    float* C = (isk ? g_k : g_q) + ((size_t)(b*NH+h)*NSP + it*128)*HD;

    float d[2][8][4];
    #pragma unroll
    for (int i=0;i<2;i++) for (int j=0;j<8;j++) for (int q=0;q<4;q++) d[i][j][q]=0.f;

    gemm128_core(A, CH, B, CH, CH, As, Bs, d);

    EPI_SETUP();
    #pragma unroll
    for (int ms = 0; ms < 2; ms++) {
        int m = wm*32 + ms*16 + g;
        #pragma unroll
        for (int ns = 0; ns < 8; ns++) {
            int n = wn*64 + ns*8 + 2*tig;
            *(float2*)&C[(size_t)m*HD + n]     = make_float2(d[ms][ns][0], d[ms][ns][1]);
            *(float2*)&C[(size_t)(m+8)*HD + n] = make_float2(d[ms][ns][2], d[ms][ns][3]);
        }
    }
}

// ---------------- 4) V GEMM: D[c'][n] = Wv * xt^T ----------------------------
__global__ void __launch_bounds__(256, 2) v_kernel(const float* __restrict__ wv) {
    __shared__ uint32_t As[128*TS], Bs[128*TS];
    int nt = blockIdx.x, h = blockIdx.y, b = blockIdx.z;

    const float* A = wv + (size_t)h*HD*CH;
    const float* B = g_xt + ((size_t)b*NSP + nt*128)*CH;
    float* C = g_v + ((size_t)(b*NH+h)*HD)*NSP + nt*128;

    float d[2][8][4];
    #pragma unroll
    for (int i=0;i<2;i++) for (int j=0;j<8;j++) for (int q=0;q<4;q++) d[i][j][q]=0.f;

    gemm128_core(A, CH, B, CH, CH, As, Bs, d);

    EPI_SETUP();
    #pragma unroll
    for (int ms = 0; ms < 2; ms++) {
        int m = wm*32 + ms*16 + g;
        #pragma unroll
        for (int ns = 0; ns < 8; ns++) {
            int n = wn*64 + ns*8 + 2*tig;
            *(float2*)&C[(size_t)m*NSP + n]     = make_float2(d[ms][ns][0], d[ms][ns][1]);
            *(float2*)&C[(size_t)(m+8)*NSP + n] = make_float2(d[ms][ns][2], d[ms][ns][3]);
        }
    }
}

// ---------------- 5) scores: D[i][j] = scale * q k^T -------------------------
__global__ void __launch_bounds__(256, 2) scores_kernel() {
    __shared__ uint32_t As[128*TS], Bs[128*TS];
    int it = blockIdx.x, jt = blockIdx.y, bh = blockIdx.z;

    const float* A = g_q + ((size_t)bh*NSP + it*128)*HD;
    const float* B = g_k + ((size_t)bh*NSP + jt*128)*HD;
    float* C = g_p + ((size_t)bh*NSP + it*128)*NSP + jt*128;

    float d[2][8][4];
    #pragma unroll
    for (int i=0;i<2;i++) for (int j=0;j<8;j++) for (int q=0;q<4;q++) d[i][j][q]=0.f;

    gemm128_core(A, HD, B, HD, HD, As, Bs, d);

    const float scale = 0.044194173824159216f;   // (256*2)^-0.5
    EPI_SETUP();
    #pragma unroll
    for (int ms = 0; ms < 2; ms++) {
        int m = wm*32 + ms*16 + g;
        #pragma unroll
        for (int ns = 0; ns < 8; ns++) {
            int n = wn*64 + ns*8 + 2*tig;
            *(float2*)&C[(size_t)m*NSP + n]     = make_float2(d[ms][ns][0]*scale, d[ms][ns][1]*scale);
            *(float2*)&C[(size_t)(m+8)*NSP + n] = make_float2(d[ms][ns][2]*scale, d[ms][ns][3]*scale);
        }
    }
}

// ---------------- 6) softmax over rows of 1024 -------------------------------
__global__ void softmax_kernel() {
    size_t row = blockIdx.x;
    float* p = g_p + row*NSP;
    int tid = threadIdx.x;

    float4 v = *(float4*)&p[tid*4];
    float m = fmaxf(fmaxf(v.x, v.y), fmaxf(v.z, v.w));
    __shared__ float red[256];
    red[tid] = m; __syncthreads();
    for (int o = 128; o > 0; o >>= 1) {
        if (tid < o) red[tid] = fmaxf(red[tid], red[tid+o]);
        __syncthreads();
    }
    m = red[0]; __syncthreads();
    v.x = __expf(v.x - m); v.y = __expf(v.y - m);
    v.z = __expf(v.z - m); v.w = __expf(v.w - m);
    float s = v.x + v.y + v.z + v.w;
    red[tid] = s; __syncthreads();
    for (int o = 128; o > 0; o >>= 1) {
        if (tid < o) red[tid] += red[tid+o];
        __syncthreads();
    }
    float inv = 1.0f / red[0];
    v.x *= inv; v.y *= inv; v.z *= inv; v.w *= inv;
    *(float4*)&p[tid*4] = v;
}

// ---------------- 7) PV: D[i][c'] = P * v^T (K = 1024) -----------------------
__global__ void __launch_bounds__(256, 2) pv_kernel() {
    __shared__ uint32_t As[128*TS], Bs[128*TS];
    int it = blockIdx.x, h = blockIdx.y, b = blockIdx.z;
    int bh = b*NH + h;

    const float* A = g_p + ((size_t)bh*NSP + it*128)*NSP;
    const float* B = g_v + (size_t)bh*HD*NSP;
    float* C = g_oat + ((size_t)b*NSP + it*128)*CH + (size_t)h*HD;

    float d[2][8][4];
    #pragma unroll
    for (int i=0;i<2;i++) for (int j=0;j<8;j++) for (int q=0;q<4;q++) d[i][j][q]=0.f;

    gemm128_core(A, NSP, B, NSP, NSP, As, Bs, d);

    EPI_SETUP();
    #pragma unroll
    for (int ms = 0; ms < 2; ms++) {
        int m = wm*32 + ms*16 + g;
        #pragma unroll
        for (int ns = 0; ns < 8; ns++) {
            int n = wn*64 + ns*8 + 2*tig;
            *(float2*)&C[(size_t)m*CH + n]     = make_float2(d[ms][ns][0], d[ms][ns][1]);
            *(float2*)&C[(size_t)(m+8)*CH + n] = make_float2(d[ms][ns][2], d[ms][ns][3]);
        }
    }
}

// ---------------- 8) proj: D[o][n] = Wp * oat^T + residual -------------------
__global__ void __launch_bounds__(256, 2) proj_kernel(const float* __restrict__ x,
                                                      const float* __restrict__ wp,
                                                      float* __restrict__ out) {
    __shared__ uint32_t As[128*TS], Bs[128*TS];
    int nt = blockIdx.x, ot = blockIdx.y, b = blockIdx.z;

    const float* A = wp + (size_t)ot*128*CH;
    const float* B = g_oat + ((size_t)b*NSP + nt*128)*CH;
    size_t cbase = ((size_t)b*CH + ot*128)*NSP + nt*128;

    float d[2][8][4];
    #pragma unroll
    for (int i=0;i<2;i++) for (int j=0;j<8;j++) for (int q=0;q<4;q++) d[i][j][q]=0.f;

    gemm128_core(A, CH, B, CH, CH, As, Bs, d);

    EPI_SETUP();
    #pragma unroll
    for (int ms = 0; ms < 2; ms++) {
        int m = wm*32 + ms*16 + g;
        #pragma unroll
        for (int ns = 0; ns < 8; ns++) {
            int n = wn*64 + ns*8 + 2*tig;
            size_t lo = cbase + (size_t)m*NSP + n;
            size_t hi = cbase + (size_t)(m+8)*NSP + n;
            float2 r0 = *(const float2*)&x[lo];
            float2 r1 = *(const float2*)&x[hi];
            *(float2*)&out[lo] = make_float2(d[ms][ns][0] + r0.x, d[ms][ns][1] + r0.y);
            *(float2*)&out[hi] = make_float2(d[ms][ns][2] + r1.x, d[ms][ns][3] + r1.y);
        }
    }
}

// -----------------------------------------------------------------------------
extern "C" void kernel_launch(void* const* d_in, const int* in_sizes, int n_in,
                              void* d_out, int out_size) {
    const float* x    = (const float*)d_in[0];
    const float* gn_w = (const float*)d_in[1];
    const float* gn_b = (const float*)d_in[2];
    const float* wq   = (const float*)d_in[3];
    const float* wk   = (const float*)d_in[4];
    const float* wv   = (const float*)d_in[5];
    const float* wp   = (const float*)d_in[6];
    float* out        = (float*)d_out;

    gn_stats_kernel<<<BATCH*NG, 256>>>(x, gn_w, gn_b);
    transpose_kernel<<<dim3(NSP/32, CH/32, BATCH), dim3(32, 8)>>>(x);
    qk_kernel    <<<dim3(NSP/128, 2*NH, BATCH), 256>>>(wq, wk);
    v_kernel     <<<dim3(NSP/128, NH,   BATCH), 256>>>(wv);
    scores_kernel<<<dim3(NSP/128, NSP/128, BATCH*NH), 256>>>();
    softmax_kernel<<<BATCH*NH*NSP, 256>>>();
    pv_kernel    <<<dim3(NSP/128, NH, BATCH), 256>>>();
    proj_kernel  <<<dim3(NSP/128, CH/128, BATCH), 256>>>(x, wp, out);
}

// round 14
// speedup vs baseline: 1.8881x; 1.0472x over previous
#include <cuda_runtime.h>
#include <stdint.h>
#include <math.h>

#define BATCH 16
#define CH    256
#define NSP   1024
#define NH    2
#define HD    128
#define NG    4
#define CPG   64

// ---------------- scratch (static device globals; no allocation) -------------
__device__ float g_scale[BATCH*CH];
__device__ float g_bias [BATCH*CH];
__device__ float g_xt[(size_t)BATCH*NSP*CH];        // normalized x (tf32-rounded), [b][n][c]
__device__ float g_q [(size_t)BATCH*NH*NSP*HD];     // [bh][i][c]   (tf32-rounded)
__device__ float g_k [(size_t)BATCH*NH*NSP*HD];     // [bh][j][c]   (tf32-rounded)
__device__ float g_v [(size_t)BATCH*NH*HD*NSP];     // [bh][c][j]   (tf32-rounded)
__device__ float g_p [(size_t)BATCH*NH*NSP*NSP];    // [bh][i][j]   (rounded after softmax)
__device__ float g_oat[(size_t)BATCH*NSP*CH];       // [b][n][c]    (tf32-rounded)
__device__ float g_wq[CH*CH], g_wk[CH*CH], g_wv[CH*CH], g_wp[CH*CH];  // rounded weights

// ---------------- helpers ----------------------------------------------------
__device__ __forceinline__ uint32_t f2tf32(float f) {
    uint32_t r; asm("cvt.rna.tf32.f32 %0, %1;" : "=r"(r) : "f"(f)); return r;
}
__device__ __forceinline__ float rnd(float f) { return __uint_as_float(f2tf32(f)); }
__device__ __forceinline__ void mma8(float d[4], const uint32_t a[4], const uint32_t b[2]) {
    asm volatile("mma.sync.aligned.m16n8k8.row.col.f32.tf32.tf32.f32 "
        "{%0,%1,%2,%3}, {%4,%5,%6,%7}, {%8,%9}, {%0,%1,%2,%3};"
        : "+f"(d[0]), "+f"(d[1]), "+f"(d[2]), "+f"(d[3])
        : "r"(a[0]), "r"(a[1]), "r"(a[2]), "r"(a[3]), "r"(b[0]), "r"(b[1]));
}
__device__ __forceinline__ void cpa16(uint32_t dst, const void* src) {
    asm volatile("cp.async.cg.shared.global [%0], [%1], 16;" :: "r"(dst), "l"(src));
}
#define CPA_COMMIT() asm volatile("cp.async.commit_group;" ::: "memory")
#define CPA_WAIT1()  asm volatile("cp.async.wait_group 1;" ::: "memory")
#define CPA_WAIT0()  asm volatile("cp.async.wait_group 0;" ::: "memory")

// SMEM tile stride in floats: 32 K-chunk + 4 pad (16B-aligned rows, no conflicts)
#define TS 36
#define TILE_U32 (128*TS)
#define GEMM_SMEM_BYTES (4*TILE_U32*4)   // 2 bufs x (A,B) = 73728 B

// ---------------- shared 128x128 GEMM core (cp.async double-buffered) --------
// C[128][128] = A[128][K] * B[128][K]^T; operands already tf32-rounded fp32.
// 256 threads; warp w: wm=w&3 (m), wn=w>>2 (n); warp tile 32(m) x 64(n).
__device__ __forceinline__ void gemm128_core(
    const float* __restrict__ A, int ldA,
    const float* __restrict__ B, int ldB,
    int K, float d[2][8][4])
{
    extern __shared__ uint32_t sms[];
    uint32_t* bufA[2] = { sms,            sms + TILE_U32 };
    uint32_t* bufB[2] = { sms + 2*TILE_U32, sms + 3*TILE_U32 };

    const int tid  = threadIdx.x;
    const int lane = tid & 31;
    const int w    = tid >> 5;
    const int wm   = w & 3, wn = w >> 2;
    const int g    = lane >> 2, tig = lane & 3;

    const int srow  = tid >> 1;          // staging row (0..127)
    const int shalf = (tid & 1) * 16;    // staging k-offset (floats)

    const float* Ar = A + (size_t)srow*ldA + shalf;
    const float* Br = B + (size_t)srow*ldB + shalf;
    uint32_t aDst[2], bDst[2];
    #pragma unroll
    for (int bi = 0; bi < 2; bi++) {
        aDst[bi] = (uint32_t)__cvta_generic_to_shared(bufA[bi] + srow*TS + shalf);
        bDst[bi] = (uint32_t)__cvta_generic_to_shared(bufB[bi] + srow*TS + shalf);
    }

    const int NC = K >> 5;

    // prologue: stage chunk 0
    #pragma unroll
    for (int f = 0; f < 4; f++) {
        cpa16(aDst[0] + f*16, Ar + f*4);
        cpa16(bDst[0] + f*16, Br + f*4);
    }
    CPA_COMMIT();

    for (int c = 0; c < NC; c++) {
        if (c + 1 < NC) {
            int nb = (c+1) & 1;
            int k0 = (c+1) << 5;
            #pragma unroll
            for (int f = 0; f < 4; f++) {
                cpa16(aDst[nb] + f*16, Ar + k0 + f*4);
                cpa16(bDst[nb] + f*16, Br + k0 + f*4);
            }
            CPA_COMMIT();
            CPA_WAIT1();
        } else {
            CPA_WAIT0();
        }
        __syncthreads();

        const uint32_t* As = bufA[c & 1];
        const uint32_t* Bs = bufB[c & 1];
        #pragma unroll
        for (int ks = 0; ks < 4; ks++) {
            uint32_t a[2][4], b[8][2];
            #pragma unroll
            for (int ms = 0; ms < 2; ms++) {
                const uint32_t* ap = As + (wm*32 + ms*16 + g)*TS + ks*8 + tig;
                a[ms][0] = ap[0];
                a[ms][1] = ap[8*TS];
                a[ms][2] = ap[4];
                a[ms][3] = ap[8*TS + 4];
            }
            #pragma unroll
            for (int ns = 0; ns < 8; ns++) {
                const uint32_t* bp = Bs + (wn*64 + ns*8 + g)*TS + ks*8 + tig;
                b[ns][0] = bp[0];
                b[ns][1] = bp[4];
            }
            #pragma unroll
            for (int ms = 0; ms < 2; ms++)
                #pragma unroll
                for (int ns = 0; ns < 8; ns++)
                    mma8(d[ms][ns], a[ms], b[ns]);
        }
        __syncthreads();
    }
}

#define EPI_SETUP() \
    const int lane = threadIdx.x & 31; const int w = threadIdx.x >> 5;          \
    const int wm = w & 3, wn = w >> 2; const int g = lane >> 2, tig = lane & 3;

#define ZERO_D() \
    float d[2][8][4];                                                            \
    _Pragma("unroll") for (int i=0;i<2;i++)                                      \
    _Pragma("unroll") for (int j=0;j<8;j++)                                      \
    _Pragma("unroll") for (int q=0;q<4;q++) d[i][j][q]=0.f;

// ---------------- 0) weight rounding -----------------------------------------
__global__ void wcvt_kernel(const float* __restrict__ wq, const float* __restrict__ wk,
                            const float* __restrict__ wv, const float* __restrict__ wp) {
    const float* src[4] = {wq, wk, wv, wp};
    float* dst0[4] = {g_wq, g_wk, g_wv, g_wp};
    int wsel = blockIdx.y;
    const float4* s = (const float4*)src[wsel];
    float4* dd = (float4*)dst0[wsel];
    int i = blockIdx.x*256 + threadIdx.x;
    float4 v = s[i];
    dd[i] = make_float4(rnd(v.x), rnd(v.y), rnd(v.z), rnd(v.w));
}

// ---------------- 1) GroupNorm stats -----------------------------------------
__global__ void gn_stats_kernel(const float* __restrict__ x,
                                const float* __restrict__ gn_w,
                                const float* __restrict__ gn_b) {
    int bg = blockIdx.x;
    int b = bg / NG, gq = bg % NG;
    const float* xp = x + ((size_t)b*CH + (size_t)gq*CPG)*NSP;
    int tid = threadIdx.x;
    float s = 0.f, s2 = 0.f;
    for (int i = tid; i < CPG*NSP/4; i += 256) {
        float4 v = ((const float4*)xp)[i];
        s  += (v.x + v.y) + (v.z + v.w);
        s2 += (v.x*v.x + v.y*v.y) + (v.z*v.z + v.w*v.w);
    }
    __shared__ float ss[256], ss2[256];
    ss[tid] = s; ss2[tid] = s2;
    __syncthreads();
    for (int o = 128; o > 0; o >>= 1) {
        if (tid < o) { ss[tid] += ss[tid+o]; ss2[tid] += ss2[tid+o]; }
        __syncthreads();
    }
    __shared__ float sh_mean, sh_rstd;
    if (tid == 0) {
        const float inv = 1.0f / (float)(CPG*NSP);
        float mean = ss[0] * inv;
        float var  = ss2[0] * inv - mean*mean;
        sh_mean = mean; sh_rstd = rsqrtf(var + 1e-5f);
    }
    __syncthreads();
    if (tid < CPG) {
        int c = gq*CPG + tid;
        float sc = sh_rstd * gn_w[c];
        g_scale[b*CH + c] = sc;
        g_bias [b*CH + c] = gn_b[c] - sh_mean * sc;
    }
}

// ---------------- 2) normalize + transpose: xt[b][n][c] (tf32) ---------------
__global__ void transpose_kernel(const float* __restrict__ x) {
    __shared__ float t[32][33];
    int b = blockIdx.z, c0 = blockIdx.y*32, n0 = blockIdx.x*32;
    int tx = threadIdx.x, ty = threadIdx.y;
    #pragma unroll
    for (int i = 0; i < 4; i++) {
        int c = c0 + ty + i*8;
        float sc = g_scale[b*CH + c], bi = g_bias[b*CH + c];
        t[ty+i*8][tx] = rnd(fmaf(x[((size_t)b*CH + c)*NSP + n0 + tx], sc, bi));
    }
    __syncthreads();
    #pragma unroll
    for (int i = 0; i < 4; i++) {
        int n = n0 + ty + i*8;
        g_xt[((size_t)b*NSP + n)*CH + c0 + tx] = t[tx][ty+i*8];
    }
}

// ---------------- 3) Q / K GEMM: D[i][c'] = xt * W^T -------------------------
__global__ void __launch_bounds__(256, 2) qk_kernel() {
    int it = blockIdx.x, yz = blockIdx.y, b = blockIdx.z;
    int h = yz >> 1, isk = yz & 1;

    const float* A = g_xt + ((size_t)b*NSP + it*128)*CH;
    const float* B = (isk ? g_wk : g_wq) + (size_t)h*HD*CH;
    float* C = (isk ? g_k : g_q) + ((size_t)(b*NH+h)*NSP + it*128)*HD;

    ZERO_D();
    gemm128_core(A, CH, B, CH, CH, d);

    EPI_SETUP();
    #pragma unroll
    for (int ms = 0; ms < 2; ms++) {
        int m = wm*32 + ms*16 + g;
        #pragma unroll
        for (int ns = 0; ns < 8; ns++) {
            int n = wn*64 + ns*8 + 2*tig;
            *(float2*)&C[(size_t)m*HD + n]     = make_float2(rnd(d[ms][ns][0]), rnd(d[ms][ns][1]));
            *(float2*)&C[(size_t)(m+8)*HD + n] = make_float2(rnd(d[ms][ns][2]), rnd(d[ms][ns][3]));
        }
    }
}

// ---------------- 4) V GEMM: D[c'][n] = Wv * xt^T ----------------------------
__global__ void __launch_bounds__(256, 2) v_kernel() {
    int nt = blockIdx.x, h = blockIdx.y, b = blockIdx.z;

    const float* A = g_wv + (size_t)h*HD*CH;
    const float* B = g_xt + ((size_t)b*NSP + nt*128)*CH;
    float* C = g_v + ((size_t)(b*NH+h)*HD)*NSP + nt*128;

    ZERO_D();
    gemm128_core(A, CH, B, CH, CH, d);

    EPI_SETUP();
    #pragma unroll
    for (int ms = 0; ms < 2; ms++) {
        int m = wm*32 + ms*16 + g;
        #pragma unroll
        for (int ns = 0; ns < 8; ns++) {
            int n = wn*64 + ns*8 + 2*tig;
            *(float2*)&C[(size_t)m*NSP + n]     = make_float2(rnd(d[ms][ns][0]), rnd(d[ms][ns][1]));
            *(float2*)&C[(size_t)(m+8)*NSP + n] = make_float2(rnd(d[ms][ns][2]), rnd(d[ms][ns][3]));
        }
    }
}

// ---------------- 5) scores: D[i][j] = scale * q k^T -------------------------
__global__ void __launch_bounds__(256, 2) scores_kernel() {
    int it = blockIdx.x, jt = blockIdx.y, bh = blockIdx.z;

    const float* A = g_q + ((size_t)bh*NSP + it*128)*HD;
    const float* B = g_k + ((size_t)bh*NSP + jt*128)*HD;
    float* C = g_p + ((size_t)bh*NSP + it*128)*NSP + jt*128;

    ZERO_D();
    gemm128_core(A, HD, B, HD, HD, d);

    const float scale = 0.044194173824159216f;   // (256*2)^-0.5
    EPI_SETUP();
    #pragma unroll
    for (int ms = 0; ms < 2; ms++) {
        int m = wm*32 + ms*16 + g;
        #pragma unroll
        for (int ns = 0; ns < 8; ns++) {
            int n = wn*64 + ns*8 + 2*tig;
            *(float2*)&C[(size_t)m*NSP + n]     = make_float2(d[ms][ns][0]*scale, d[ms][ns][1]*scale);
            *(float2*)&C[(size_t)(m+8)*NSP + n] = make_float2(d[ms][ns][2]*scale, d[ms][ns][3]*scale);
        }
    }
}

// ---------------- 6) softmax: warp per row of 1024, tf32-rounded store -------
__global__ void softmax_kernel() {
    int wid = threadIdx.x >> 5, lane = threadIdx.x & 31;
    size_t row = (size_t)blockIdx.x*8 + wid;
    float* p = g_p + row*NSP;

    float4 v[8];
    #pragma unroll
    for (int u = 0; u < 8; u++) v[u] = ((float4*)p)[lane + u*32];

    float m = -1e30f;
    #pragma unroll
    for (int u = 0; u < 8; u++)
        m = fmaxf(m, fmaxf(fmaxf(v[u].x, v[u].y), fmaxf(v[u].z, v[u].w)));
    #pragma unroll
    for (int o = 16; o > 0; o >>= 1) m = fmaxf(m, __shfl_xor_sync(0xffffffffu, m, o));

    float s = 0.f;
    #pragma unroll
    for (int u = 0; u < 8; u++) {
        v[u].x = __expf(v[u].x - m); v[u].y = __expf(v[u].y - m);
        v[u].z = __expf(v[u].z - m); v[u].w = __expf(v[u].w - m);
        s += (v[u].x + v[u].y) + (v[u].z + v[u].w);
    }
    #pragma unroll
    for (int o = 16; o > 0; o >>= 1) s += __shfl_xor_sync(0xffffffffu, s, o);

    float inv = 1.0f / s;
    #pragma unroll
    for (int u = 0; u < 8; u++)
        ((float4*)p)[lane + u*32] = make_float4(rnd(v[u].x*inv), rnd(v[u].y*inv),
                                                rnd(v[u].z*inv), rnd(v[u].w*inv));
}

// ---------------- 7) PV: D[i][c'] = P * v^T (K = 1024) -----------------------
__global__ void __launch_bounds__(256, 2) pv_kernel() {
    int it = blockIdx.x, h = blockIdx.y, b = blockIdx.z;
    int bh = b*NH + h;

    const float* A = g_p + ((size_t)bh*NSP + it*128)*NSP;
    const float* B = g_v + (size_t)bh*HD*NSP;
    float* C = g_oat + ((size_t)b*NSP + it*128)*CH + (size_t)h*HD;

    ZERO_D();
    gemm128_core(A, NSP, B, NSP, NSP, d);

    EPI_SETUP();
    #pragma unroll
    for (int ms = 0; ms < 2; ms++) {
        int m = wm*32 + ms*16 + g;
        #pragma unroll
        for (int ns = 0; ns < 8; ns++) {
            int n = wn*64 + ns*8 + 2*tig;
            *(float2*)&C[(size_t)m*CH + n]     = make_float2(rnd(d[ms][ns][0]), rnd(d[ms][ns][1]));
            *(float2*)&C[(size_t)(m+8)*CH + n] = make_float2(rnd(d[ms][ns][2]), rnd(d[ms][ns][3]));
        }
    }
}

// ---------------- 8) proj: D[o][n] = Wp * oat^T + residual -------------------
__global__ void __launch_bounds__(256, 2) proj_kernel(const float* __restrict__ x,
                                                      float* __restrict__ out) {
    int nt = blockIdx.x, ot = blockIdx.y, b = blockIdx.z;

    const float* A = g_wp + (size_t)ot*128*CH;
    const float* B = g_oat + ((size_t)b*NSP + nt*128)*CH;
    size_t cbase = ((size_t)b*CH + ot*128)*NSP + nt*128;

    ZERO_D();
    gemm128_core(A, CH, B, CH, CH, d);

    EPI_SETUP();
    #pragma unroll
    for (int ms = 0; ms < 2; ms++) {
        int m = wm*32 + ms*16 + g;
        #pragma unroll
        for (int ns = 0; ns < 8; ns++) {
            int n = wn*64 + ns*8 + 2*tig;
            size_t lo = cbase + (size_t)m*NSP + n;
            size_t hi = cbase + (size_t)(m+8)*NSP + n;
            float2 r0 = *(const float2*)&x[lo];
            float2 r1 = *(const float2*)&x[hi];
            *(float2*)&out[lo] = make_float2(d[ms][ns][0] + r0.x, d[ms][ns][1] + r0.y);
            *(float2*)&out[hi] = make_float2(d[ms][ns][2] + r1.x, d[ms][ns][3] + r1.y);
        }
    }
}

// -----------------------------------------------------------------------------
extern "C" void kernel_launch(void* const* d_in, const int* in_sizes, int n_in,
                              void* d_out, int out_size) {
    const float* x    = (const float*)d_in[0];
    const float* gn_w = (const float*)d_in[1];
    const float* gn_b = (const float*)d_in[2];
    const float* wq   = (const float*)d_in[3];
    const float* wk   = (const float*)d_in[4];
    const float* wv   = (const float*)d_in[5];
    const float* wp   = (const float*)d_in[6];
    float* out        = (float*)d_out;

    cudaFuncSetAttribute(qk_kernel,     cudaFuncAttributeMaxDynamicSharedMemorySize, GEMM_SMEM_BYTES);
    cudaFuncSetAttribute(v_kernel,      cudaFuncAttributeMaxDynamicSharedMemorySize, GEMM_SMEM_BYTES);
    cudaFuncSetAttribute(scores_kernel, cudaFuncAttributeMaxDynamicSharedMemorySize, GEMM_SMEM_BYTES);
    cudaFuncSetAttribute(pv_kernel,     cudaFuncAttributeMaxDynamicSharedMemorySize, GEMM_SMEM_BYTES);
    cudaFuncSetAttribute(proj_kernel,   cudaFuncAttributeMaxDynamicSharedMemorySize, GEMM_SMEM_BYTES);

    wcvt_kernel    <<<dim3(64, 4), 256>>>(wq, wk, wv, wp);
    gn_stats_kernel<<<BATCH*NG, 256>>>(x, gn_w, gn_b);
    transpose_kernel<<<dim3(NSP/32, CH/32, BATCH), dim3(32, 8)>>>(x);
    qk_kernel    <<<dim3(NSP/128, 2*NH, BATCH), 256, GEMM_SMEM_BYTES>>>();
    v_kernel     <<<dim3(NSP/128, NH,   BATCH), 256, GEMM_SMEM_BYTES>>>();
    scores_kernel<<<dim3(NSP/128, NSP/128, BATCH*NH), 256, GEMM_SMEM_BYTES>>>();
    softmax_kernel<<<BATCH*NH*NSP/8, 256>>>();
    pv_kernel    <<<dim3(NSP/128, NH, BATCH), 256, GEMM_SMEM_BYTES>>>();
    proj_kernel  <<<dim3(NSP/128, CH/128, BATCH), 256, GEMM_SMEM_BYTES>>>(x, out);
}

// round 17
// speedup vs baseline: 2.3123x; 1.2247x over previous
#include <cuda_runtime.h>
#include <stdint.h>
#include <math.h>

#define BATCH 16
#define CH    256
#define NSP   1024
#define NH    2
#define HD    128
#define NG    4
#define CPG   64

// ---------------- scratch (static device globals; no allocation) -------------
__device__ float g_scale[BATCH*CH];
__device__ float g_bias [BATCH*CH];
__device__ float g_xt[(size_t)BATCH*NSP*CH];        // normalized x (tf32-rounded), [b][n][c]
__device__ float g_q [(size_t)BATCH*NH*NSP*HD];     // [bh][i][c]   (tf32-rounded)
__device__ float g_k [(size_t)BATCH*NH*NSP*HD];     // [bh][j][c]   (tf32-rounded)
__device__ float g_v [(size_t)BATCH*NH*HD*NSP];     // [bh][c][j]   (tf32-rounded)
__device__ float g_oat[(size_t)BATCH*NSP*CH];       // [b][n][c]    (tf32-rounded)
__device__ float g_wq[CH*CH], g_wk[CH*CH], g_wv[CH*CH], g_wp[CH*CH];  // rounded weights

// ---------------- helpers ----------------------------------------------------
__device__ __forceinline__ uint32_t f2tf32(float f) {
    uint32_t r; asm("cvt.rna.tf32.f32 %0, %1;" : "=r"(r) : "f"(f)); return r;
}
__device__ __forceinline__ float rnd(float f) { return __uint_as_float(f2tf32(f)); }
__device__ __forceinline__ void mma8(float d[4], const uint32_t a[4], const uint32_t b[2]) {
    asm volatile("mma.sync.aligned.m16n8k8.row.col.f32.tf32.tf32.f32 "
        "{%0,%1,%2,%3}, {%4,%5,%6,%7}, {%8,%9}, {%0,%1,%2,%3};"
        : "+f"(d[0]), "+f"(d[1]), "+f"(d[2]), "+f"(d[3])
        : "r"(a[0]), "r"(a[1]), "r"(a[2]), "r"(a[3]), "r"(b[0]), "r"(b[1]));
}
__device__ __forceinline__ void cpa16(uint32_t dst, const void* src) {
    asm volatile("cp.async.cg.shared.global [%0], [%1], 16;" :: "r"(dst), "l"(src));
}
#define CPA_COMMIT() asm volatile("cp.async.commit_group;" ::: "memory")
#define CPA_WAIT1()  asm volatile("cp.async.wait_group 1;" ::: "memory")
#define CPA_WAIT0()  asm volatile("cp.async.wait_group 0;" ::: "memory")

#define TS 36
#define TILE_U32 (128*TS)
#define GEMM_SMEM_BYTES (4*TILE_U32*4)   // 73728 B

// stage one [128][32] chunk (this thread's 16 floats) via cp.async
__device__ __forceinline__ void stage16(uint32_t dst, const float* src) {
    #pragma unroll
    for (int f = 0; f < 4; f++) cpa16(dst + f*16, src + f*4);
}

// one 32-wide K-chunk of MMAs: As/Bs are [128][TS] tf32 chunks
__device__ __forceinline__ void mma_chunk(const uint32_t* As, const uint32_t* Bs,
                                          float d[2][8][4],
                                          int wm, int wn, int g, int tig) {
    #pragma unroll
    for (int ks = 0; ks < 4; ks++) {
        uint32_t a[2][4], b[8][2];
        #pragma unroll
        for (int ms = 0; ms < 2; ms++) {
            const uint32_t* ap = As + (wm*32 + ms*16 + g)*TS + ks*8 + tig;
            a[ms][0] = ap[0];
            a[ms][1] = ap[8*TS];
            a[ms][2] = ap[4];
            a[ms][3] = ap[8*TS + 4];
        }
        #pragma unroll
        for (int ns = 0; ns < 8; ns++) {
            const uint32_t* bp = Bs + (wn*64 + ns*8 + g)*TS + ks*8 + tig;
            b[ns][0] = bp[0];
            b[ns][1] = bp[4];
        }
        #pragma unroll
        for (int ms = 0; ms < 2; ms++)
            #pragma unroll
            for (int ns = 0; ns < 8; ns++)
                mma8(d[ms][ns], a[ms], b[ns]);
    }
}

// ---------------- shared 128x128 GEMM core (cp.async double-buffered) --------
__device__ __forceinline__ void gemm128_core(
    const float* __restrict__ A, int ldA,
    const float* __restrict__ B, int ldB,
    int K, float d[2][8][4])
{
    extern __shared__ uint32_t sms[];
    uint32_t* bufA[2] = { sms,              sms + TILE_U32 };
    uint32_t* bufB[2] = { sms + 2*TILE_U32, sms + 3*TILE_U32 };

    const int tid  = threadIdx.x;
    const int lane = tid & 31;
    const int w    = tid >> 5;
    const int wm   = w & 3, wn = w >> 2;
    const int g    = lane >> 2, tig = lane & 3;
    const int srow  = tid >> 1;
    const int shalf = (tid & 1) * 16;

    const float* Ar = A + (size_t)srow*ldA + shalf;
    const float* Br = B + (size_t)srow*ldB + shalf;
    uint32_t aDst[2], bDst[2];
    #pragma unroll
    for (int bi = 0; bi < 2; bi++) {
        aDst[bi] = (uint32_t)__cvta_generic_to_shared(bufA[bi] + srow*TS + shalf);
        bDst[bi] = (uint32_t)__cvta_generic_to_shared(bufB[bi] + srow*TS + shalf);
    }

    const int NC = K >> 5;
    stage16(aDst[0], Ar); stage16(bDst[0], Br);
    CPA_COMMIT();

    for (int c = 0; c < NC; c++) {
        if (c + 1 < NC) {
            int nb = (c+1) & 1, k0 = (c+1) << 5;
            stage16(aDst[nb], Ar + k0); stage16(bDst[nb], Br + k0);
            CPA_COMMIT();
            CPA_WAIT1();
        } else CPA_WAIT0();
        __syncthreads();
        mma_chunk(bufA[c & 1], bufB[c & 1], d, wm, wn, g, tig);
        __syncthreads();
    }
}

#define EPI_SETUP() \
    const int lane = threadIdx.x & 31; const int w = threadIdx.x >> 5;          \
    const int wm = w & 3, wn = w >> 2; const int g = lane >> 2, tig = lane & 3;

#define ZERO_D(d) \
    _Pragma("unroll") for (int i=0;i<2;i++)                                      \
    _Pragma("unroll") for (int j=0;j<8;j++)                                      \
    _Pragma("unroll") for (int q=0;q<4;q++) d[i][j][q]=0.f;

// ---------------- 0) weight rounding -----------------------------------------
__global__ void wcvt_kernel(const float* __restrict__ wq, const float* __restrict__ wk,
                            const float* __restrict__ wv, const float* __restrict__ wp) {
    const float* src[4] = {wq, wk, wv, wp};
    float* dst0[4] = {g_wq, g_wk, g_wv, g_wp};
    int wsel = blockIdx.y;
    const float4* s = (const float4*)src[wsel];
    float4* dd = (float4*)dst0[wsel];
    int i = blockIdx.x*256 + threadIdx.x;
    float4 v = s[i];
    dd[i] = make_float4(rnd(v.x), rnd(v.y), rnd(v.z), rnd(v.w));
}

// ---------------- 1) GroupNorm stats -----------------------------------------
__global__ void gn_stats_kernel(const float* __restrict__ x,
                                const float* __restrict__ gn_w,
                                const float* __restrict__ gn_b) {
    int bg = blockIdx.x;
    int b = bg / NG, gq = bg % NG;
    const float* xp = x + ((size_t)b*CH + (size_t)gq*CPG)*NSP;
    int tid = threadIdx.x;
    float s = 0.f, s2 = 0.f;
    for (int i = tid; i < CPG*NSP/4; i += 256) {
        float4 v = ((const float4*)xp)[i];
        s  += (v.x + v.y) + (v.z + v.w);
        s2 += (v.x*v.x + v.y*v.y) + (v.z*v.z + v.w*v.w);
    }
    __shared__ float ss[256], ss2[256];
    ss[tid] = s; ss2[tid] = s2;
    __syncthreads();
    for (int o = 128; o > 0; o >>= 1) {
        if (tid < o) { ss[tid] += ss[tid+o]; ss2[tid] += ss2[tid+o]; }
        __syncthreads();
    }
    __shared__ float sh_mean, sh_rstd;
    if (tid == 0) {
        const float inv = 1.0f / (float)(CPG*NSP);
        float mean = ss[0] * inv;
        float var  = ss2[0] * inv - mean*mean;
        sh_mean = mean; sh_rstd = rsqrtf(var + 1e-5f);
    }
    __syncthreads();
    if (tid < CPG) {
        int c = gq*CPG + tid;
        float sc = sh_rstd * gn_w[c];
        g_scale[b*CH + c] = sc;
        g_bias [b*CH + c] = gn_b[c] - sh_mean * sc;
    }
}

// ---------------- 2) normalize + transpose: xt[b][n][c] (tf32) ---------------
__global__ void transpose_kernel(const float* __restrict__ x) {
    __shared__ float t[32][33];
    int b = blockIdx.z, c0 = blockIdx.y*32, n0 = blockIdx.x*32;
    int tx = threadIdx.x, ty = threadIdx.y;
    #pragma unroll
    for (int i = 0; i < 4; i++) {
        int c = c0 + ty + i*8;
        float sc = g_scale[b*CH + c], bi = g_bias[b*CH + c];
        t[ty+i*8][tx] = rnd(fmaf(x[((size_t)b*CH + c)*NSP + n0 + tx], sc, bi));
    }
    __syncthreads();
    #pragma unroll
    for (int i = 0; i < 4; i++) {
        int n = n0 + ty + i*8;
        g_xt[((size_t)b*NSP + n)*CH + c0 + tx] = t[tx][ty+i*8];
    }
}

// ---------------- 3) Q / K GEMM ----------------------------------------------
__global__ void __launch_bounds__(256, 2) qk_kernel() {
    int it = blockIdx.x, yz = blockIdx.y, b = blockIdx.z;
    int h = yz >> 1, isk = yz & 1;

    const float* A = g_xt + ((size_t)b*NSP + it*128)*CH;
    const float* B = (isk ? g_wk : g_wq) + (size_t)h*HD*CH;
    float* C = (isk ? g_k : g_q) + ((size_t)(b*NH+h)*NSP + it*128)*HD;

    float d[2][8][4]; ZERO_D(d);
    gemm128_core(A, CH, B, CH, CH, d);

    EPI_SETUP();
    #pragma unroll
    for (int ms = 0; ms < 2; ms++) {
        int m = wm*32 + ms*16 + g;
        #pragma unroll
        for (int ns = 0; ns < 8; ns++) {
            int n = wn*64 + ns*8 + 2*tig;
            *(float2*)&C[(size_t)m*HD + n]     = make_float2(rnd(d[ms][ns][0]), rnd(d[ms][ns][1]));
            *(float2*)&C[(size_t)(m+8)*HD + n] = make_float2(rnd(d[ms][ns][2]), rnd(d[ms][ns][3]));
        }
    }
}

// ---------------- 4) V GEMM ---------------------------------------------------
__global__ void __launch_bounds__(256, 2) v_kernel() {
    int nt = blockIdx.x, h = blockIdx.y, b = blockIdx.z;

    const float* A = g_wv + (size_t)h*HD*CH;
    const float* B = g_xt + ((size_t)b*NSP + nt*128)*CH;
    float* C = g_v + ((size_t)(b*NH+h)*HD)*NSP + nt*128;

    float d[2][8][4]; ZERO_D(d);
    gemm128_core(A, CH, B, CH, CH, d);

    EPI_SETUP();
    #pragma unroll
    for (int ms = 0; ms < 2; ms++) {
        int m = wm*32 + ms*16 + g;
        #pragma unroll
        for (int ns = 0; ns < 8; ns++) {
            int n = wn*64 + ns*8 + 2*tig;
            *(float2*)&C[(size_t)m*NSP + n]     = make_float2(rnd(d[ms][ns][0]), rnd(d[ms][ns][1]));
            *(float2*)&C[(size_t)(m+8)*NSP + n] = make_float2(rnd(d[ms][ns][2]), rnd(d[ms][ns][3]));
        }
    }
}

// ---------------- 5) fused flash attention ------------------------------------
// smem: Qs[4 chunks] + Ps[4 chunks] + KV[2 chunks] + reductions
#define FL_SMEM_BYTES (10*TILE_U32*4 + (256+256+384)*4)

__global__ void __launch_bounds__(256, 1) flash_kernel() {
    extern __shared__ uint32_t sms[];
    uint32_t* Qs = sms;                       // 4 * TILE_U32
    uint32_t* Ps = sms + 4*TILE_U32;          // 4 * TILE_U32
    uint32_t* KVb[2] = { sms + 8*TILE_U32, sms + 9*TILE_U32 };
    float* redmax = (float*)(sms + 10*TILE_U32);   // [2][128]
    float* redsum = redmax + 256;                  // [2][128]
    float* mrow   = redsum + 256;                  // [128]
    float* lrow   = mrow + 128;
    float* arow   = lrow + 128;

    const int tid = threadIdx.x, lane = tid & 31, w = tid >> 5;
    const int wm = w & 3, wn = w >> 2;
    const int g = lane >> 2, tig = lane & 3;
    const int it = blockIdx.x, h = blockIdx.y, b = blockIdx.z;
    const int bh = b*NH + h;
    const int srow = tid >> 1, shalf = (tid & 1) * 16;

    const float* Qg = g_q + ((size_t)bh*NSP + (size_t)it*128)*HD;
    const float* Kg = g_k + (size_t)bh*NSP*HD;
    const float* Vg = g_v + (size_t)bh*HD*NSP;

    // stage Q once (4 chunks)
    #pragma unroll
    for (int c = 0; c < 4; c++) {
        uint32_t dst = (uint32_t)__cvta_generic_to_shared(Qs + c*TILE_U32 + srow*TS + shalf);
        stage16(dst, Qg + (size_t)srow*HD + c*32 + shalf);
    }
    CPA_COMMIT();
    if (tid < 128) { mrow[tid] = -1e30f; lrow[tid] = 0.f; }

    uint32_t kvDst[2];
    #pragma unroll
    for (int bi = 0; bi < 2; bi++)
        kvDst[bi] = (uint32_t)__cvta_generic_to_shared(KVb[bi] + srow*TS + shalf);

    float dO[2][8][4]; ZERO_D(dO);
    const float scale = 0.044194173824159216f;   // (256*2)^-0.5

    for (int jt = 0; jt < 8; jt++) {
        // ======== S = Q K^T over this j-tile ========
        const float* Kt = Kg + (size_t)(jt*128)*HD + (size_t)srow*HD + shalf;
        float dS[2][8][4]; ZERO_D(dS);

        stage16(kvDst[0], Kt);
        CPA_COMMIT();
        #pragma unroll
        for (int c = 0; c < 4; c++) {
            if (c < 3) { stage16(kvDst[(c+1)&1], Kt + (c+1)*32); CPA_COMMIT(); CPA_WAIT1(); }
            else CPA_WAIT0();
            __syncthreads();
            mma_chunk(Qs + c*TILE_U32, KVb[c&1], dS, wm, wn, g, tig);
            __syncthreads();
        }

        // scale
        #pragma unroll
        for (int ms = 0; ms < 2; ms++)
            #pragma unroll
            for (int ns = 0; ns < 8; ns++)
                #pragma unroll
                for (int q = 0; q < 4; q++) dS[ms][ns][q] *= scale;

        // ======== online softmax ========
        // rows: r(ms,hf) = wm*32 + ms*16 + hf*8 + g ; hf=0 -> q0,q1 ; hf=1 -> q2,q3
        float lm[2][2];
        #pragma unroll
        for (int ms = 0; ms < 2; ms++) {
            lm[ms][0] = -1e30f; lm[ms][1] = -1e30f;
            #pragma unroll
            for (int ns = 0; ns < 8; ns++) {
                lm[ms][0] = fmaxf(lm[ms][0], fmaxf(dS[ms][ns][0], dS[ms][ns][1]));
                lm[ms][1] = fmaxf(lm[ms][1], fmaxf(dS[ms][ns][2], dS[ms][ns][3]));
            }
        }
        #pragma unroll
        for (int o = 1; o <= 2; o <<= 1)
            #pragma unroll
            for (int ms = 0; ms < 2; ms++) {
                lm[ms][0] = fmaxf(lm[ms][0], __shfl_xor_sync(0xffffffffu, lm[ms][0], o));
                lm[ms][1] = fmaxf(lm[ms][1], __shfl_xor_sync(0xffffffffu, lm[ms][1], o));
            }
        if (tig == 0) {
            #pragma unroll
            for (int ms = 0; ms < 2; ms++) {
                redmax[wn*128 + wm*32 + ms*16 + g]     = lm[ms][0];
                redmax[wn*128 + wm*32 + ms*16 + 8 + g] = lm[ms][1];
            }
        }
        __syncthreads();

        float mnew[2][2];
        #pragma unroll
        for (int ms = 0; ms < 2; ms++)
            #pragma unroll
            for (int hf = 0; hf < 2; hf++) {
                int r = wm*32 + ms*16 + hf*8 + g;
                mnew[ms][hf] = fmaxf(mrow[r], fmaxf(redmax[r], redmax[128 + r]));
            }

        float ls[2][2] = {{0.f,0.f},{0.f,0.f}};
        #pragma unroll
        for (int ms = 0; ms < 2; ms++)
            #pragma unroll
            for (int ns = 0; ns < 8; ns++) {
                dS[ms][ns][0] = __expf(dS[ms][ns][0] - mnew[ms][0]);
                dS[ms][ns][1] = __expf(dS[ms][ns][1] - mnew[ms][0]);
                dS[ms][ns][2] = __expf(dS[ms][ns][2] - mnew[ms][1]);
                dS[ms][ns][3] = __expf(dS[ms][ns][3] - mnew[ms][1]);
                ls[ms][0] += dS[ms][ns][0] + dS[ms][ns][1];
                ls[ms][1] += dS[ms][ns][2] + dS[ms][ns][3];
            }
        #pragma unroll
        for (int o = 1; o <= 2; o <<= 1)
            #pragma unroll
            for (int ms = 0; ms < 2; ms++) {
                ls[ms][0] += __shfl_xor_sync(0xffffffffu, ls[ms][0], o);
                ls[ms][1] += __shfl_xor_sync(0xffffffffu, ls[ms][1], o);
            }
        if (tig == 0) {
            #pragma unroll
            for (int ms = 0; ms < 2; ms++) {
                redsum[wn*128 + wm*32 + ms*16 + g]     = ls[ms][0];
                redsum[wn*128 + wm*32 + ms*16 + 8 + g] = ls[ms][1];
            }
        }
        __syncthreads();

        if (wn == 0 && tig == 0) {
            #pragma unroll
            for (int ms = 0; ms < 2; ms++)
                #pragma unroll
                for (int hf = 0; hf < 2; hf++) {
                    int r = wm*32 + ms*16 + hf*8 + g;
                    float mn = mnew[ms][hf];
                    float al = __expf(mrow[r] - mn);
                    lrow[r] = al*lrow[r] + redsum[r] + redsum[128 + r];
                    mrow[r] = mn;
                    arow[r] = al;
                }
        }
        __syncthreads();

        // ======== O rescale + P store (tf32) ========
        #pragma unroll
        for (int ms = 0; ms < 2; ms++) {
            float a0 = arow[wm*32 + ms*16 + g];
            float a1 = arow[wm*32 + ms*16 + 8 + g];
            #pragma unroll
            for (int ns = 0; ns < 8; ns++) {
                dO[ms][ns][0] *= a0; dO[ms][ns][1] *= a0;
                dO[ms][ns][2] *= a1; dO[ms][ns][3] *= a1;
            }
        }
        #pragma unroll
        for (int ms = 0; ms < 2; ms++) {
            int r0 = wm*32 + ms*16 + g, r1 = r0 + 8;
            #pragma unroll
            for (int ns = 0; ns < 8; ns++) {
                int jl = wn*64 + ns*8 + 2*tig;
                int chunk = jl >> 5, off = jl & 31;
                uint32_t* pc = Ps + chunk*TILE_U32;
                *(uint2*)&pc[r0*TS + off] = make_uint2(f2tf32(dS[ms][ns][0]), f2tf32(dS[ms][ns][1]));
                *(uint2*)&pc[r1*TS + off] = make_uint2(f2tf32(dS[ms][ns][2]), f2tf32(dS[ms][ns][3]));
            }
        }
        __syncthreads();

        // ======== O += P V^T over this j-tile ========
        const float* Vt = Vg + (size_t)srow*NSP + (size_t)jt*128 + shalf;
        stage16(kvDst[0], Vt);
        CPA_COMMIT();
        #pragma unroll
        for (int c = 0; c < 4; c++) {
            if (c < 3) { stage16(kvDst[(c+1)&1], Vt + (c+1)*32); CPA_COMMIT(); CPA_WAIT1(); }
            else CPA_WAIT0();
            __syncthreads();
            mma_chunk(Ps + c*TILE_U32, KVb[c&1], dO, wm, wn, g, tig);
            __syncthreads();
        }
    }

    // ======== epilogue: divide by l, round, store ========
    float* C = g_oat + ((size_t)b*NSP + (size_t)it*128)*CH + (size_t)h*HD;
    #pragma unroll
    for (int ms = 0; ms < 2; ms++) {
        int r0 = wm*32 + ms*16 + g, r1 = r0 + 8;
        float i0 = 1.0f / lrow[r0], i1 = 1.0f / lrow[r1];
        #pragma unroll
        for (int ns = 0; ns < 8; ns++) {
            int n = wn*64 + ns*8 + 2*tig;
            *(float2*)&C[(size_t)r0*CH + n] = make_float2(rnd(dO[ms][ns][0]*i0), rnd(dO[ms][ns][1]*i0));
            *(float2*)&C[(size_t)r1*CH + n] = make_float2(rnd(dO[ms][ns][2]*i1), rnd(dO[ms][ns][3]*i1));
        }
    }
}

// ---------------- 6) proj: D[o][n] = Wp * oat^T + residual -------------------
__global__ void __launch_bounds__(256, 2) proj_kernel(const float* __restrict__ x,
                                                      float* __restrict__ out) {
    int nt = blockIdx.x, ot = blockIdx.y, b = blockIdx.z;

    const float* A = g_wp + (size_t)ot*128*CH;
    const float* B = g_oat + ((size_t)b*NSP + nt*128)*CH;
    size_t cbase = ((size_t)b*CH + ot*128)*NSP + nt*128;

    float d[2][8][4]; ZERO_D(d);
    gemm128_core(A, CH, B, CH, CH, d);

    EPI_SETUP();
    #pragma unroll
    for (int ms = 0; ms < 2; ms++) {
        int m = wm*32 + ms*16 + g;
        #pragma unroll
        for (int ns = 0; ns < 8; ns++) {
            int n = wn*64 + ns*8 + 2*tig;
            size_t lo = cbase + (size_t)m*NSP + n;
            size_t hi = cbase + (size_t)(m+8)*NSP + n;
            float2 r0 = *(const float2*)&x[lo];
            float2 r1 = *(const float2*)&x[hi];
            *(float2*)&out[lo] = make_float2(d[ms][ns][0] + r0.x, d[ms][ns][1] + r0.y);
            *(float2*)&out[hi] = make_float2(d[ms][ns][2] + r1.x, d[ms][ns][3] + r1.y);
        }
    }
}

// -----------------------------------------------------------------------------
extern "C" void kernel_launch(void* const* d_in, const int* in_sizes, int n_in,
                              void* d_out, int out_size) {
    const float* x    = (const float*)d_in[0];
    const float* gn_w = (const float*)d_in[1];
    const float* gn_b = (const float*)d_in[2];
    const float* wq   = (const float*)d_in[3];
    const float* wk   = (const float*)d_in[4];
    const float* wv   = (const float*)d_in[5];
    const float* wp   = (const float*)d_in[6];
    float* out        = (float*)d_out;

    cudaFuncSetAttribute(qk_kernel,    cudaFuncAttributeMaxDynamicSharedMemorySize, GEMM_SMEM_BYTES);
    cudaFuncSetAttribute(v_kernel,     cudaFuncAttributeMaxDynamicSharedMemorySize, GEMM_SMEM_BYTES);
    cudaFuncSetAttribute(flash_kernel, cudaFuncAttributeMaxDynamicSharedMemorySize, FL_SMEM_BYTES);
    cudaFuncSetAttribute(proj_kernel,  cudaFuncAttributeMaxDynamicSharedMemorySize, GEMM_SMEM_BYTES);

    wcvt_kernel    <<<dim3(64, 4), 256>>>(wq, wk, wv, wp);
    gn_stats_kernel<<<BATCH*NG, 256>>>(x, gn_w, gn_b);
    transpose_kernel<<<dim3(NSP/32, CH/32, BATCH), dim3(32, 8)>>>(x);
    qk_kernel    <<<dim3(NSP/128, 2*NH, BATCH), 256, GEMM_SMEM_BYTES>>>();
    v_kernel     <<<dim3(NSP/128, NH,   BATCH), 256, GEMM_SMEM_BYTES>>>();
    flash_kernel <<<dim3(NSP/128, NH, BATCH), 256, FL_SMEM_BYTES>>>();
    proj_kernel  <<<dim3(NSP/128, CH/128, BATCH), 256, GEMM_SMEM_BYTES>>>(x, out);
}